// round 10
// baseline (speedup 1.0000x reference)
#include <cuda_runtime.h>
#include <cuda_bf16.h>
#include <cstdint>

#define NN 2048
#define BB 64
#define TT 512
#define CTAS 128
#define THREADS 512
#define PITCHB 4112                 // 2048*2 + 16 bytes, conflict-free ldmatrix rows

// ---- shared memory layout ----
#define OFF_WHI 0
#define OFF_WLO (16 * PITCHB)               // 65792
#define OFF_SPK (32 * PITCHB)               // 131584
#define SPK_STRIDE 68                       // u32 words per spike row (padded)
#define OFF_MEM (OFF_SPK + 64 * SPK_STRIDE * 4)   // 148992
#define OFF_RED (OFF_MEM + 64 * 16 * 4)           // 153088
#define OFF_LUT (OFF_RED + 8 * 64 * 16 * 4)       // 185856
#define SMEM_TOTAL (OFF_LUT + 128)                // 185984

// ---- persistent device state ----
__device__ __align__(16) __nv_bfloat16 g_Whi[NN * NN];    // [n][k] = 0.1*eff^T, hi
__device__ __align__(16) __nv_bfloat16 g_Wlo[NN * NN];    // residual
__device__ __align__(16) uint32_t g_spk0[BB * (NN / 32)]; // bit-permuted packed spikes
__device__ __align__(16) uint32_t g_spk1[BB * (NN / 32)];
__device__ uint32_t g_bar;

// Spike bit permutation: within each 16-bit half (h = k>=16), local c = k&15 sits at
//   np(c) = ((c&7)>>1)*4 + (c&1) + 2*((c>>3)&1)
// so nibble q of a half = bits {k=2q, 2q+1, 2q+8, 2q+9}: one lane's A-pair bits.

// ---- helpers ----
__device__ __forceinline__ uint32_t smem_u32(const void* p) {
    uint32_t a;
    asm("{ .reg .u64 t; cvta.to.shared.u64 t, %1; cvt.u32.u64 %0, t; }" : "=r"(a) : "l"(p));
    return a;
}

__device__ __forceinline__ void ldsm2(uint32_t* r, uint32_t addr) {
    asm volatile("ldmatrix.sync.aligned.m8n8.x2.shared.b16 {%0,%1}, [%2];"
                 : "=r"(r[0]), "=r"(r[1]) : "r"(addr));
}

__device__ __forceinline__ void mma_bf16(float* c, const uint32_t* a, uint32_t b0, uint32_t b1) {
    asm volatile(
        "mma.sync.aligned.m16n8k16.row.col.f32.bf16.bf16.f32 "
        "{%0,%1,%2,%3},{%4,%5,%6,%7},{%8,%9},{%0,%1,%2,%3};"
        : "+f"(c[0]), "+f"(c[1]), "+f"(c[2]), "+f"(c[3])
        : "r"(a[0]), "r"(a[1]), "r"(a[2]), "r"(a[3]), "r"(b0), "r"(b1));
}

// ---- prep: transpose + zero diag + 0.1 scale + bf16 hi/lo split, plus state init ----
__global__ void prep_kernel(const float* __restrict__ rec) {
    __shared__ float tile[32][33];
    int k = blockIdx.y * 32 + threadIdx.y;
    int n = blockIdx.x * 32 + threadIdx.x;
    tile[threadIdx.y][threadIdx.x] = rec[k * NN + n];

    int fb = blockIdx.y * gridDim.x + blockIdx.x;
    int ft = threadIdx.y * 32 + threadIdx.x;
    if (fb < 4)      g_spk0[fb * 1024 + ft] = 0u;
    else if (fb < 8) g_spk1[(fb - 4) * 1024 + ft] = 0u;
    else if (fb == 8 && ft == 0) g_bar = 0u;

    __syncthreads();
    int nn = blockIdx.x * 32 + threadIdx.y;
    int kk = blockIdx.y * 32 + threadIdx.x;
    float w = tile[threadIdx.x][threadIdx.y];      // rec[kk][nn]
    float v = (nn == kk) ? 0.0f : 0.1f * w;
    __nv_bfloat16 hi = __float2bfloat16(v);
    float resid = v - __bfloat162float(hi);
    g_Whi[nn * NN + kk] = hi;
    g_Wlo[nn * NN + kk] = __float2bfloat16(resid);
}

// ---- persistent RSNN kernel: 128 CTAs, 16 warps, warp = (k-eighth, n-half) ----
__global__ void __launch_bounds__(THREADS, 1)
rsnn_kernel(const float* __restrict__ x, float* __restrict__ out) {
    extern __shared__ char smem[];
    const uint32_t sbase = smem_u32(smem);

    const int tid = threadIdx.x;
    const int wid = tid >> 5;
    const int lane = tid & 31;
    const int n0 = blockIdx.x * 16;

    const int kh = wid >> 1;            // k-eighth (8 u32 spike words)
    const int nh = wid & 1;             // n-half (8 columns)

    // ---- load weight slice into SMEM (hi + lo, pitched) — init only ----
    for (int i = tid; i < 16 * 256; i += THREADS) {
        int row = i >> 8, c = i & 255;
        *(uint4*)(smem + OFF_WHI + row * PITCHB + c * 16) =
            *(const uint4*)(g_Whi + (size_t)(n0 + row) * NN + c * 8);
        *(uint4*)(smem + OFF_WLO + row * PITCHB + c * 16) =
            *(const uint4*)(g_Wlo + (size_t)(n0 + row) * NN + c * 8);
    }
    for (int i = tid; i < 64 * 16; i += THREADS)
        ((float*)(smem + OFF_MEM))[i] = 0.0f;
    // nibble -> (a_low, a_high) bf16x2 LUT; conflict-free bank sweep
    if (tid < 16) {
        uint2 e;
        e.x = ((tid & 1) ? 0x00003F80u : 0u) | ((tid & 2) ? 0x3F800000u : 0u);
        e.y = ((tid & 4) ? 0x00003F80u : 0u) | ((tid & 8) ? 0x3F800000u : 0u);
        ((uint2*)(smem + OFF_LUT))[tid] = e;
    }
    __syncthreads();

    // per-thread constants (GEMM)
    const int rowq = lane >> 2;           // 0..7
    const int q4 = (lane & 3) * 4;        // nibble shift within a 16-bit half
    const int lc = lane & 3;
    uint32_t ldsm_off;
    {
        int grp = (lane >> 3) & 1;                    // k-octet select within k16
        int row = nh * 8 + (lane & 7);                // local neuron row (n-half)
        ldsm_off = row * PITCHB + grp * 16;
    }

    // ---- hoist B fragments (hi + lo, this warp's k-eighth x n-half) to regs ----
    uint32_t bhr[8][2][2], blr[8][2][2];
    #pragma unroll
    for (int j = 0; j < 8; ++j) {
        const int widx = (kh << 3) + j;
        #pragma unroll
        for (int h = 0; h < 2; ++h) {
            const int kt = widx * 2 + h;
            ldsm2(bhr[j][h], sbase + OFF_WHI + ldsm_off + kt * 32);
            ldsm2(blr[j][h], sbase + OFF_WLO + ldsm_off + kt * 32);
        }
    }

    // per-thread constants (epilogue: all 512 threads, 2 cols each)
    const int eb = tid >> 3;              // batch row 0..63
    const int cp = tid & 7;               // logical col pair 0..7
    const int ec = cp * 2;
    const int wsel = n0 >> 5;
    const int hsh = ((n0 >> 4) & 1) * 16;

    int npos[2];
    uint32_t pmask[2];
    #pragma unroll
    for (int i = 0; i < 2; ++i) {
        int c = ec + i;
        npos[i] = ((c & 7) >> 1) * 4 + (c & 1) + 2 * ((c >> 3) & 1);
        pmask[i] = 1u << (hsh + npos[i]);
    }
    // swizzled reduce offset (pair swizzle: phys = (cp + ((eb&2)<<1)) & 7)
    const int red_off = eb * 16 + ((cp + ((eb & 2) << 1)) & 7) * 2;

    uint32_t* const spkS = (uint32_t*)(smem + OFF_SPK);
    float* const memS = (float*)(smem + OFF_MEM);
    float* const redS = (float*)(smem + OFF_RED);
    const uint2* const lutS = (const uint2*)(smem + OFF_LUT);

    for (int t = 0; t < TT; ++t) {
        const uint32_t* gsrc = (t & 1) ? g_spk1 : g_spk0;
        uint32_t* gdst = (t & 1) ? g_spk0 : g_spk1;

        // ---- prefetch x for this step ----
        float2 xv = __ldg((const float2*)(x + ((size_t)eb * TT + t) * NN + n0 + ec));

        // ---- stage packed spikes [64 x 64 u32] -> padded SMEM rows ----
        {
            const uint4* src = (const uint4*)gsrc;
            #pragma unroll
            for (int i = tid; i < 1024; i += THREADS) {
                int row = i >> 4, c4 = i & 15;
                uint4 v = __ldcg(src + i);
                *(uint4*)(smem + OFF_SPK + (row * SPK_STRIDE + c4 * 4) * 4) = v;
            }
        }
        __syncthreads();

        // hoist prev-spike word (reset mask): no spkS reads after dump-sync
        const uint32_t pw = spkS[eb * SPK_STRIDE + wsel];

        // ---- GEMM: warp = (k-eighth, n-half), B in registers ----
        float acc[4][4];
        #pragma unroll
        for (int m = 0; m < 4; ++m)
            #pragma unroll
            for (int e = 0; e < 4; ++e) acc[m][e] = 0.0f;

        #pragma unroll
        for (int j = 0; j < 8; ++j) {
            const int widx = (kh << 3) + j;           // u32 spike word index
            #pragma unroll
            for (int m = 0; m < 4; ++m) {
                const uint32_t w0 = spkS[(m * 16 + rowq) * SPK_STRIDE + widx];
                const uint32_t w1 = spkS[(m * 16 + rowq + 8) * SPK_STRIDE + widx];
                #pragma unroll
                for (int h = 0; h < 2; ++h) {
                    uint2 u0 = lutS[(w0 >> (h * 16 + q4)) & 0xFu];
                    uint2 u1 = lutS[(w1 >> (h * 16 + q4)) & 0xFu];
                    uint32_t a[4] = {u0.x, u1.x, u0.y, u1.y};
                    mma_bf16(acc[m], a, bhr[j][h][0], bhr[j][h][1]);
                    mma_bf16(acc[m], a, blr[j][h][0], blr[j][h][1]);
                }
            }
        }

        // ---- dump: two n-half warps fill disjoint cols of region kh (swizzled) ----
        {
            float* pwrt = redS + kh * 1024;
            #pragma unroll
            for (int m = 0; m < 4; ++m) {
                const int mycp = nh * 4 + lc;
                const int r0 = m * 16 + rowq;
                const int sw0 = ((mycp + ((r0 & 2) << 1)) & 7) * 2;
                const int r1 = r0 + 8;
                const int sw1 = ((mycp + ((r1 & 2) << 1)) & 7) * 2;
                *(float2*)(pwrt + r0 * 16 + sw0) = make_float2(acc[m][0], acc[m][1]);
                *(float2*)(pwrt + r1 * 16 + sw1) = make_float2(acc[m][2], acc[m][3]);
            }
        }
        __syncthreads();

        // ---- reduce 8 partials + LIF epilogue (all 512 threads, 2 cols each) ----
        float2 s = *(float2*)(redS + red_off);
        #pragma unroll
        for (int w = 1; w < 8; ++w) {
            float2 p = *(float2*)(redS + w * 1024 + red_off);
            s.x += p.x; s.y += p.y;
        }

        float2 mv = *(float2*)(memS + eb * 16 + ec);
        float cur0 = xv.x + s.x, cur1 = xv.y + s.y;
        float m0 = (pw & pmask[0]) ? cur0 : fmaf(0.96f, mv.x, cur0);
        float m1 = (pw & pmask[1]) ? cur1 : fmaf(0.96f, mv.y, cur1);
        unsigned s0 = (m0 >= 0.5f), s1 = (m1 >= 0.5f);

        *(float2*)(memS + eb * 16 + ec) = make_float2(m0, m1);

        // pack new spike bits (permuted positions) -> u16 per (batch row, CTA)
        unsigned v = (s0 << npos[0]) | (s1 << npos[1]);
        v |= __shfl_xor_sync(0xFFFFFFFFu, v, 1);
        v |= __shfl_xor_sync(0xFFFFFFFFu, v, 2);
        v |= __shfl_xor_sync(0xFFFFFFFFu, v, 4);
        if ((tid & 7) == 0)
            ((uint16_t*)gdst)[eb * 128 + blockIdx.x] = (uint16_t)v;

        // ---- all spikes published -> arrive; out stores overlap the poll ----
        __syncthreads();
        if (tid == 0)
            asm volatile("red.release.gpu.global.add.u32 [%0], 1;" :: "l"(&g_bar) : "memory");

        *(float2*)(out + ((size_t)eb * TT + t) * NN + n0 + ec) =
            make_float2((float)s0, (float)s1);

        // per-warp poll (no trailing block sync; next stage-sync restores order)
        {
            const unsigned tgt = (unsigned)(CTAS * (t + 1));
            if (lane == 0) {
                unsigned bv;
                do {
                    asm volatile("ld.acquire.gpu.global.u32 %0, [%1];"
                                 : "=r"(bv) : "l"(&g_bar) : "memory");
                } while (bv < tgt);
            }
            __syncwarp();
        }
    }
}

// ---- launch ----
extern "C" void kernel_launch(void* const* d_in, const int* in_sizes, int n_in,
                              void* d_out, int out_size) {
    const float* x = (const float*)d_in[0];
    const float* rec = (const float*)d_in[1];
    if (n_in >= 2 && in_sizes[0] == NN * NN) {
        x = (const float*)d_in[1];
        rec = (const float*)d_in[0];
    }
    float* out = (float*)d_out;

    cudaFuncSetAttribute(rsnn_kernel, cudaFuncAttributeMaxDynamicSharedMemorySize, SMEM_TOTAL);

    dim3 cg(NN / 32, NN / 32), cb(32, 32);
    prep_kernel<<<cg, cb>>>(rec);
    rsnn_kernel<<<CTAS, THREADS, SMEM_TOTAL>>>(x, out);
}

// round 11
// speedup vs baseline: 1.1015x; 1.1015x over previous
#include <cuda_runtime.h>
#include <cuda_bf16.h>
#include <cstdint>

#define NN 2048
#define BB 64
#define TT 512
#define CTAS 128
#define THREADS 256
#define PITCHB 4112                 // 2048*2 + 16 bytes, conflict-free ldmatrix rows

// ---- shared memory layout ----
#define OFF_WHI 0
#define OFF_WLO (16 * PITCHB)               // 65792
#define OFF_SPK (32 * PITCHB)               // 131584
#define SPK_STRIDE 68                       // u32 words per spike row (padded)
#define OFF_XCH (OFF_SPK + 64 * SPK_STRIDE * 4)   // 148992  (8 regions x 8 rows x 24 floats)
#define OFF_LUT (OFF_XCH + 6144)                  // 155136
#define SMEM_TOTAL (OFF_LUT + 128)                // 155264

// ---- persistent device state ----
__device__ __align__(16) __nv_bfloat16 g_Whi[NN * NN];    // [n][k] = 0.1*eff^T, hi
__device__ __align__(16) __nv_bfloat16 g_Wlo[NN * NN];    // residual
__device__ __align__(16) uint32_t g_spk0[BB * (NN / 32)]; // bit-permuted packed spikes
__device__ __align__(16) uint32_t g_spk1[BB * (NN / 32)];
__device__ uint32_t g_bar;

// Spike bit permutation: within each 16-bit half, local col c sits at
//   np(c) = ((c&7)>>1)*4 + (c&1) + 2*((c>>3)&1)
// so nibble q = bits of cols {2q, 2q+1, 2q+8, 2q+9} — exactly one lane's MMA
// A-pair bits AND one lane's MMA output columns.

// ---- helpers ----
__device__ __forceinline__ uint32_t smem_u32(const void* p) {
    uint32_t a;
    asm("{ .reg .u64 t; cvta.to.shared.u64 t, %1; cvt.u32.u64 %0, t; }" : "=r"(a) : "l"(p));
    return a;
}

__device__ __forceinline__ void ldsm4(uint32_t* r, uint32_t addr) {
    asm volatile("ldmatrix.sync.aligned.m8n8.x4.shared.b16 {%0,%1,%2,%3}, [%4];"
                 : "=r"(r[0]), "=r"(r[1]), "=r"(r[2]), "=r"(r[3]) : "r"(addr));
}

__device__ __forceinline__ void mma_bf16(float* c, const uint32_t* a, uint32_t b0, uint32_t b1) {
    asm volatile(
        "mma.sync.aligned.m16n8k16.row.col.f32.bf16.bf16.f32 "
        "{%0,%1,%2,%3},{%4,%5,%6,%7},{%8,%9},{%0,%1,%2,%3};"
        : "+f"(c[0]), "+f"(c[1]), "+f"(c[2]), "+f"(c[3])
        : "r"(a[0]), "r"(a[1]), "r"(a[2]), "r"(a[3]), "r"(b0), "r"(b1));
}

// ---- prep: transpose + zero diag + 0.1 scale + bf16 hi/lo split, plus state init ----
__global__ void prep_kernel(const float* __restrict__ rec) {
    __shared__ float tile[32][33];
    int k = blockIdx.y * 32 + threadIdx.y;
    int n = blockIdx.x * 32 + threadIdx.x;
    tile[threadIdx.y][threadIdx.x] = rec[k * NN + n];

    int fb = blockIdx.y * gridDim.x + blockIdx.x;
    int ft = threadIdx.y * 32 + threadIdx.x;
    if (fb < 4)      g_spk0[fb * 1024 + ft] = 0u;
    else if (fb < 8) g_spk1[(fb - 4) * 1024 + ft] = 0u;
    else if (fb == 8 && ft == 0) g_bar = 0u;

    __syncthreads();
    int nn = blockIdx.x * 32 + threadIdx.y;
    int kk = blockIdx.y * 32 + threadIdx.x;
    float w = tile[threadIdx.x][threadIdx.y];      // rec[kk][nn]
    float v = (nn == kk) ? 0.0f : 0.1f * w;
    __nv_bfloat16 hi = __float2bfloat16(v);
    float resid = v - __bfloat162float(hi);
    g_Whi[nn * NN + kk] = hi;
    g_Wlo[nn * NN + kk] = __float2bfloat16(resid);
}

// ---- persistent RSNN kernel: 128 CTAs, 8 warps, warp = (m-tile, k-half) ----
__global__ void __launch_bounds__(THREADS)
rsnn_kernel(const float* __restrict__ x, float* __restrict__ out) {
    extern __shared__ char smem[];
    const uint32_t sbase = smem_u32(smem);

    const int tid = threadIdx.x;
    const int wid = tid >> 5;
    const int lane = tid & 31;
    const int n0 = blockIdx.x * 16;

    const int m = wid & 3;              // m16 tile (batch rows m*16..m*16+15)
    const int kh = wid >> 2;            // k-half (32 u32 spike words)

    // ---- load weight slice into SMEM once (hi + lo, pitched) ----
    for (int i = tid; i < 16 * 256; i += THREADS) {
        int row = i >> 8, c = i & 255;
        *(uint4*)(smem + OFF_WHI + row * PITCHB + c * 16) =
            *(const uint4*)(g_Whi + (size_t)(n0 + row) * NN + c * 8);
        *(uint4*)(smem + OFF_WLO + row * PITCHB + c * 16) =
            *(const uint4*)(g_Wlo + (size_t)(n0 + row) * NN + c * 8);
    }
    // nibble -> (a_low, a_high) bf16x2 LUT; conflict-free bank sweep
    if (tid < 16) {
        uint2 e;
        e.x = ((tid & 1) ? 0x00003F80u : 0u) | ((tid & 2) ? 0x3F800000u : 0u);
        e.y = ((tid & 4) ? 0x00003F80u : 0u) | ((tid & 8) ? 0x3F800000u : 0u);
        ((uint2*)(smem + OFF_LUT))[tid] = e;
    }
    __syncthreads();

    // per-thread constants
    const int rowq = lane >> 2;           // 0..7
    const int q = lane & 3;
    const int q4 = q * 4;
    uint32_t ldsm_off;
    {
        int grp = lane >> 3;                          // 8x8 matrix select
        int row = ((grp >> 1) << 3) + (lane & 7);     // local neuron row 0..15
        int koff = (grp & 1) * 8;
        ldsm_off = row * PITCHB + koff * 2;
    }
    const int row_own = m * 16 + kh * 8 + rowq;       // batch row this thread finalizes
    const int wsel = n0 >> 5;
    const int hsh = ((n0 >> 4) & 1) * 16;
    const int psh = hsh + q4;                         // prev-spike nibble shift

    // exchange offsets (stride-24 rows: conflict-free STS.64 / LDS.64)
    const int xo_dump = ((m * 2 + (1 - kh)) * 8 + rowq) * 24 + 2 * q;
    const int xo_read = ((m * 2 + kh) * 8 + rowq) * 24 + 2 * q;

    uint32_t* const spkS = (uint32_t*)(smem + OFF_SPK);
    float* const xchS = (float*)(smem + OFF_XCH);
    const uint2* const lutS = (const uint2*)(smem + OFF_LUT);

    // membrane state lives in registers for the whole run
    float mv[4] = {0.f, 0.f, 0.f, 0.f};

    for (int t = 0; t < TT; ++t) {
        const uint32_t* gsrc = (t & 1) ? g_spk1 : g_spk0;
        uint32_t* gdst = (t & 1) ? g_spk0 : g_spk1;

        // ---- prefetch x for this thread's row/cols ----
        const float* xrow = x + ((size_t)row_own * TT + t) * NN + n0;
        float2 xa = __ldg((const float2*)(xrow + 2 * q));
        float2 xb = __ldg((const float2*)(xrow + 8 + 2 * q));

        // ---- stage packed spikes [64 x 64 u32] -> padded SMEM rows ----
        {
            const uint4* src = (const uint4*)gsrc;
            #pragma unroll
            for (int i = tid; i < 1024; i += THREADS) {
                int row = i >> 4, c4 = i & 15;
                uint4 v = __ldcg(src + i);
                *(uint4*)(smem + OFF_SPK + (row * SPK_STRIDE + c4 * 4) * 4) = v;
            }
        }
        __syncthreads();

        // prev-spike word for reset mask (own row)
        const uint32_t pw = spkS[row_own * SPK_STRIDE + wsel];

        // ---- GEMM: warp = (m-tile, k-half); 8 acc chains of depth 32 ----
        float accH[2][2][4], accL[2][2][4];
        #pragma unroll
        for (int h = 0; h < 2; ++h)
            #pragma unroll
            for (int nh = 0; nh < 2; ++nh)
                #pragma unroll
                for (int e = 0; e < 4; ++e) { accH[h][nh][e] = 0.f; accL[h][nh][e] = 0.f; }

        #pragma unroll 4
        for (int j = 0; j < 32; ++j) {
            const int widx = kh * 32 + j;             // u32 spike word index
            const uint32_t w0 = spkS[(m * 16 + rowq) * SPK_STRIDE + widx];
            const uint32_t w1 = spkS[(m * 16 + rowq + 8) * SPK_STRIDE + widx];
            #pragma unroll
            for (int h = 0; h < 2; ++h) {
                const int kt = widx * 2 + h;
                uint32_t bh[4], bl[4];
                ldsm4(bh, sbase + OFF_WHI + ldsm_off + kt * 32);
                ldsm4(bl, sbase + OFF_WLO + ldsm_off + kt * 32);
                uint2 u0 = lutS[(w0 >> (h * 16 + q4)) & 0xFu];
                uint2 u1 = lutS[(w1 >> (h * 16 + q4)) & 0xFu];
                uint32_t a[4] = {u0.x, u1.x, u0.y, u1.y};
                mma_bf16(accH[h][0], a, bh[0], bh[1]);
                mma_bf16(accH[h][1], a, bh[2], bh[3]);
                mma_bf16(accL[h][0], a, bl[0], bl[1]);
                mma_bf16(accL[h][1], a, bl[2], bl[3]);
            }
        }

        // ---- fold 8 chains -> own-row vals (vo) + other-row vals (vx) ----
        // c = 0..3 -> cols {2q, 2q+1, 2q+8, 2q+9}; eo = own e-base, ex = other
        const int eo = kh * 2, ex = 2 - kh * 2;
        float vo[4], vx[4];
        #pragma unroll
        for (int c = 0; c < 4; ++c) {
            const int nh = c >> 1, i = c & 1;
            vo[c] = (accH[0][nh][eo + i] + accH[1][nh][eo + i]) +
                    (accL[0][nh][eo + i] + accL[1][nh][eo + i]);
            vx[c] = (accH[0][nh][ex + i] + accH[1][nh][ex + i]) +
                    (accL[0][nh][ex + i] + accL[1][nh][ex + i]);
        }

        // dump the non-owned half-rows for the partner k-half warp
        *(float2*)(xchS + xo_dump) = make_float2(vx[0], vx[1]);
        *(float2*)(xchS + xo_dump + 8) = make_float2(vx[2], vx[3]);
        __syncthreads();

        // combine with partner's partial
        float2 pa = *(float2*)(xchS + xo_read);
        float2 pb = *(float2*)(xchS + xo_read + 8);
        float s0f = vo[0] + pa.x, s1f = vo[1] + pa.y;
        float s2f = vo[2] + pb.x, s3f = vo[3] + pb.y;

        // ---- LIF update (4 cols of row_own), mem in registers ----
        float cur0 = xa.x + s0f, cur1 = xa.y + s1f;
        float cur2 = xb.x + s2f, cur3 = xb.y + s3f;
        float m0 = ((pw >> psh) & 1u) ? cur0 : fmaf(0.96f, mv[0], cur0);
        float m1 = ((pw >> psh) & 2u) ? cur1 : fmaf(0.96f, mv[1], cur1);
        float m2 = ((pw >> psh) & 4u) ? cur2 : fmaf(0.96f, mv[2], cur2);
        float m3 = ((pw >> psh) & 8u) ? cur3 : fmaf(0.96f, mv[3], cur3);
        mv[0] = m0; mv[1] = m1; mv[2] = m2; mv[3] = m3;

        unsigned s0 = (m0 >= 0.5f), s1 = (m1 >= 0.5f);
        unsigned s2 = (m2 >= 0.5f), s3 = (m3 >= 0.5f);

        // publish spikes: nibble q of the row word (permuted layout)
        unsigned v = (s0 | (s1 << 1) | (s2 << 2) | (s3 << 3)) << q4;
        v |= __shfl_xor_sync(0xFFFFFFFFu, v, 1);
        v |= __shfl_xor_sync(0xFFFFFFFFu, v, 2);
        if (q == 0)
            ((uint16_t*)gdst)[row_own * 128 + blockIdx.x] = (uint16_t)v;

        // ---- all spikes published -> arrive; out stores overlap the poll ----
        __syncthreads();
        if (tid == 0)
            asm volatile("red.release.gpu.global.add.u32 [%0], 1;" :: "l"(&g_bar) : "memory");

        float* orow = out + ((size_t)row_own * TT + t) * NN + n0;
        *(float2*)(orow + 2 * q) = make_float2((float)s0, (float)s1);
        *(float2*)(orow + 8 + 2 * q) = make_float2((float)s2, (float)s3);

        if (tid == 0) {
            const unsigned tgt = (unsigned)(CTAS * (t + 1));
            unsigned bv;
            do {
                asm volatile("ld.acquire.gpu.global.u32 %0, [%1];" : "=r"(bv) : "l"(&g_bar) : "memory");
            } while (bv < tgt);
        }
        __syncthreads();
    }
}

// ---- launch ----
extern "C" void kernel_launch(void* const* d_in, const int* in_sizes, int n_in,
                              void* d_out, int out_size) {
    const float* x = (const float*)d_in[0];
    const float* rec = (const float*)d_in[1];
    if (n_in >= 2 && in_sizes[0] == NN * NN) {
        x = (const float*)d_in[1];
        rec = (const float*)d_in[0];
    }
    float* out = (float*)d_out;

    cudaFuncSetAttribute(rsnn_kernel, cudaFuncAttributeMaxDynamicSharedMemorySize, SMEM_TOTAL);

    dim3 cg(NN / 32, NN / 32), cb(32, 32);
    prep_kernel<<<cg, cb>>>(rec);
    rsnn_kernel<<<CTAS, THREADS, SMEM_TOTAL>>>(x, out);
}

// round 12
// speedup vs baseline: 1.1616x; 1.0546x over previous
#include <cuda_runtime.h>
#include <cuda_bf16.h>
#include <cstdint>

#define NN 2048
#define BB 64
#define TT 512
#define CTAS 256
#define THREADS 256
#define PITCHB 4112                 // 2048*2 + 16 bytes, conflict-free ldmatrix rows

// ---- shared memory layout (per CTA ~97 KB -> 2 CTAs/SM) ----
#define OFF_WHI 0
#define OFF_WLO (8 * PITCHB)                // 32896
#define OFF_SPK (16 * PITCHB)               // 65792
#define SPK_STRIDE 68                       // u32 words per spike row (padded)
#define OFF_RED (OFF_SPK + 64 * SPK_STRIDE * 4)   // 83200
#define OFF_LUT (OFF_RED + 8 * 64 * 8 * 4)        // 99584
#define SMEM_TOTAL (OFF_LUT + 128)                // 99712

// ---- persistent device state ----
__device__ __align__(16) __nv_bfloat16 g_Whi[NN * NN];    // [n][k] = 0.1*eff^T, hi
__device__ __align__(16) __nv_bfloat16 g_Wlo[NN * NN];    // residual
// packed spikes, permuted layout; byte b of row r = CTA b's 8 neurons
__device__ __align__(16) uint32_t g_spk0[BB * (NN / 32)];
__device__ __align__(16) uint32_t g_spk1[BB * (NN / 32)];
__device__ uint32_t g_bar;

// Spike bit permutation: within each 16-bit half, local col c sits at
//   np(c) = ((c&7)>>1)*4 + (c&1) + 2*((c>>3)&1)
// nibble q = cols {2q,2q+1,2q+8,2q+9} (one lane's A-pair bits).
// CTA c owns group g=c>>1, local cols side*4 + {0,1,2,3,8,9,10,11}
// (side=c&1) == byte (c&3) of spike word (c>>2).

// ---- helpers ----
__device__ __forceinline__ uint32_t smem_u32(const void* p) {
    uint32_t a;
    asm("{ .reg .u64 t; cvta.to.shared.u64 t, %1; cvt.u32.u64 %0, t; }" : "=r"(a) : "l"(p));
    return a;
}

__device__ __forceinline__ void ldsm2(uint32_t* r, uint32_t addr) {
    asm volatile("ldmatrix.sync.aligned.m8n8.x2.shared.b16 {%0,%1}, [%2];"
                 : "=r"(r[0]), "=r"(r[1]) : "r"(addr));
}

__device__ __forceinline__ void mma_bf16(float* c, const uint32_t* a, uint32_t b0, uint32_t b1) {
    asm volatile(
        "mma.sync.aligned.m16n8k16.row.col.f32.bf16.bf16.f32 "
        "{%0,%1,%2,%3},{%4,%5,%6,%7},{%8,%9},{%0,%1,%2,%3};"
        : "+f"(c[0]), "+f"(c[1]), "+f"(c[2]), "+f"(c[3])
        : "r"(a[0]), "r"(a[1]), "r"(a[2]), "r"(a[3]), "r"(b0), "r"(b1));
}

// ---- prep: transpose + zero diag + 0.1 scale + bf16 hi/lo split, plus state init ----
__global__ void prep_kernel(const float* __restrict__ rec) {
    __shared__ float tile[32][33];
    int k = blockIdx.y * 32 + threadIdx.y;
    int n = blockIdx.x * 32 + threadIdx.x;
    tile[threadIdx.y][threadIdx.x] = rec[k * NN + n];

    int fb = blockIdx.y * gridDim.x + blockIdx.x;
    int ft = threadIdx.y * 32 + threadIdx.x;
    if (fb < 4)      g_spk0[fb * 1024 + ft] = 0u;
    else if (fb < 8) g_spk1[(fb - 4) * 1024 + ft] = 0u;
    else if (fb == 8 && ft == 0) g_bar = 0u;

    __syncthreads();
    int nn = blockIdx.x * 32 + threadIdx.y;
    int kk = blockIdx.y * 32 + threadIdx.x;
    float w = tile[threadIdx.x][threadIdx.y];      // rec[kk][nn]
    float v = (nn == kk) ? 0.0f : 0.1f * w;
    __nv_bfloat16 hi = __float2bfloat16(v);
    float resid = v - __bfloat162float(hi);
    g_Whi[nn * NN + kk] = hi;
    g_Wlo[nn * NN + kk] = __float2bfloat16(resid);
}

// ---- persistent RSNN: 256 CTAs (2/SM), 8 neurons each, 8 warps ----
__global__ void __launch_bounds__(THREADS, 2)
rsnn_kernel(const float* __restrict__ x, float* __restrict__ out) {
    extern __shared__ char smem[];
    const uint32_t sbase = smem_u32(smem);

    const int tid = threadIdx.x;
    const int wid = tid >> 5;           // warp = k-eighth (8 u32 spike words)
    const int lane = tid & 31;
    const int c = blockIdx.x;           // CTA id 0..255
    const int g = c >> 1;               // 16-neuron group
    const int side = c & 1;             // low/high byte of the group's half-word

    // ---- load 8 weight rows (owned neurons) into SMEM (hi + lo) ----
    for (int i = tid; i < 2 * 8 * 256; i += THREADS) {   // 2 mats x 8 rows x 256 uint4
        int mat = i >> 11;
        int qq = i & 2047;
        int j = qq >> 8;                 // SMEM B row 0..7
        int c16 = qq & 255;
        int lcol = side * 4 + ((j >> 2) << 3) + (j & 3); // owned neuron (group-local)
        const uint4* gsrc = (const uint4*)(mat ? g_Wlo : g_Whi);
        uint4 v = gsrc[(size_t)(g * 16 + lcol) * (NN / 8) + c16];
        *(uint4*)(smem + (mat ? OFF_WLO : OFF_WHI) + j * PITCHB + c16 * 16) = v;
    }
    // nibble -> (a_low, a_high) bf16x2 LUT; conflict-free bank sweep
    if (tid < 16) {
        uint2 e;
        e.x = ((tid & 1) ? 0x00003F80u : 0u) | ((tid & 2) ? 0x3F800000u : 0u);
        e.y = ((tid & 4) ? 0x00003F80u : 0u) | ((tid & 8) ? 0x3F800000u : 0u);
        ((uint2*)(smem + OFF_LUT))[tid] = e;
    }
    __syncthreads();

    // per-thread constants (GEMM)
    const int rowq = lane >> 2;           // 0..7
    const int q = lane & 3;
    const int q4 = q * 4;
    const uint32_t ldsm_off = (lane & 7) * PITCHB + ((lane >> 3) & 1) * 16;

    // ---- hoist B fragments (hi + lo, this warp's k-eighth) into registers ----
    uint32_t bhr[8][2][2], blr[8][2][2];
    #pragma unroll
    for (int j = 0; j < 8; ++j) {
        const int widx = (wid << 3) + j;
        #pragma unroll
        for (int h = 0; h < 2; ++h) {
            const int kt = widx * 2 + h;
            ldsm2(bhr[j][h], sbase + OFF_WHI + ldsm_off + kt * 32);
            ldsm2(blr[j][h], sbase + OFF_WLO + ldsm_off + kt * 32);
        }
    }

    // per-thread constants (epilogue: 256 threads = 64 rows x 4 col-pairs)
    const int er = tid >> 2;              // batch row 0..63
    // epilogue col-pair index == q (lane&3) by construction
    const int colglob = g * 16 + side * 4 + ((q >> 1) << 3) + ((q & 1) << 1);
    const int bitbase = ((q & 1) << 2) | (q & 2);   // {0,4,2,6}
    const int wsel = c >> 2;                        // own word in staged table
    const int psh = ((c & 3) << 3) + bitbase;       // own bits in that word
    const int red_rd = er * 8 + ((q + er) & 3) * 2; // swizzled reduce offset

    uint32_t* const spkS = (uint32_t*)(smem + OFF_SPK);
    float* const redS = (float*)(smem + OFF_RED);
    const uint2* const lutS = (const uint2*)(smem + OFF_LUT);

    // membrane state lives in registers for the whole run
    float mv0 = 0.f, mv1 = 0.f;

    for (int t = 0; t < TT; ++t) {
        const uint32_t* gsrc = (t & 1) ? g_spk1 : g_spk0;
        uint32_t* gdst = (t & 1) ? g_spk0 : g_spk1;

        // ---- prefetch x (own row, own col pair) ----
        float2 xv = __ldg((const float2*)(x + ((size_t)er * TT + t) * NN + colglob));

        // ---- stage packed spikes [64 x 64 u32] -> padded SMEM rows ----
        {
            const uint4* src = (const uint4*)gsrc;
            #pragma unroll
            for (int i = tid; i < 1024; i += THREADS) {
                int row = i >> 4, c4 = i & 15;
                uint4 v = __ldcg(src + i);
                *(uint4*)(smem + OFF_SPK + (row * SPK_STRIDE + c4 * 4) * 4) = v;
            }
        }
        __syncthreads();

        // prev-spike word for reset mask (own row/cols)
        const uint32_t pw = spkS[er * SPK_STRIDE + wsel];

        // ---- GEMM: warp = k-eighth, 4 m-tiles, n8; B in registers ----
        float acc[4][4];
        #pragma unroll
        for (int m = 0; m < 4; ++m)
            #pragma unroll
            for (int e = 0; e < 4; ++e) acc[m][e] = 0.0f;

        #pragma unroll
        for (int j = 0; j < 8; ++j) {
            const int widx = (wid << 3) + j;
            #pragma unroll
            for (int m = 0; m < 4; ++m) {
                const uint32_t w0 = spkS[(m * 16 + rowq) * SPK_STRIDE + widx];
                const uint32_t w1 = spkS[(m * 16 + rowq + 8) * SPK_STRIDE + widx];
                #pragma unroll
                for (int h = 0; h < 2; ++h) {
                    uint2 u0 = lutS[(w0 >> (h * 16 + q4)) & 0xFu];
                    uint2 u1 = lutS[(w1 >> (h * 16 + q4)) & 0xFu];
                    uint32_t a[4] = {u0.x, u1.x, u0.y, u1.y};
                    mma_bf16(acc[m], a, bhr[j][h][0], bhr[j][h][1]);
                    mma_bf16(acc[m], a, blr[j][h][0], blr[j][h][1]);
                }
            }
        }

        // ---- dump per-warp partials (swizzled cols: conflict-free STS.64) ----
        {
            float* reg = redS + wid * 512;
            #pragma unroll
            for (int m = 0; m < 4; ++m) {
                const int r0 = m * 16 + rowq;
                const int sw = ((q + r0) & 3) * 2;       // (r0+8 same mod 4)
                *(float2*)(reg + r0 * 8 + sw) = make_float2(acc[m][0], acc[m][1]);
                *(float2*)(reg + (r0 + 8) * 8 + sw) = make_float2(acc[m][2], acc[m][3]);
            }
        }
        __syncthreads();

        // ---- reduce 8 partials + LIF epilogue ----
        float2 s = *(float2*)(redS + red_rd);
        #pragma unroll
        for (int w = 1; w < 8; ++w) {
            float2 p = *(float2*)(redS + w * 512 + red_rd);
            s.x += p.x; s.y += p.y;
        }

        float cur0 = xv.x + s.x, cur1 = xv.y + s.y;
        float m0 = ((pw >> psh) & 1u) ? cur0 : fmaf(0.96f, mv0, cur0);
        float m1 = ((pw >> psh) & 2u) ? cur1 : fmaf(0.96f, mv1, cur1);
        mv0 = m0; mv1 = m1;
        unsigned s0 = (m0 >= 0.5f), s1 = (m1 >= 0.5f);

        // publish own byte (permuted bit positions within the byte)
        unsigned v = (s0 | (s1 << 1)) << bitbase;
        v |= __shfl_xor_sync(0xFFFFFFFFu, v, 1);
        v |= __shfl_xor_sync(0xFFFFFFFFu, v, 2);
        if (q == 0)
            ((uint8_t*)gdst)[er * 256 + c] = (uint8_t)v;

        // ---- all spikes published -> arrive; out stores overlap the poll ----
        __syncthreads();
        if (tid == 0)
            asm volatile("red.release.gpu.global.add.u32 [%0], 1;" :: "l"(&g_bar) : "memory");

        *(float2*)(out + ((size_t)er * TT + t) * NN + colglob) =
            make_float2((float)s0, (float)s1);

        if (tid == 0) {
            const unsigned tgt = (unsigned)(CTAS * (t + 1));
            unsigned bv;
            do {
                asm volatile("ld.acquire.gpu.global.u32 %0, [%1];" : "=r"(bv) : "l"(&g_bar) : "memory");
                if (bv >= tgt) break;
                __nanosleep(64);
            } while (true);
        }
        __syncthreads();
    }
}

// ---- launch ----
extern "C" void kernel_launch(void* const* d_in, const int* in_sizes, int n_in,
                              void* d_out, int out_size) {
    const float* x = (const float*)d_in[0];
    const float* rec = (const float*)d_in[1];
    if (n_in >= 2 && in_sizes[0] == NN * NN) {
        x = (const float*)d_in[1];
        rec = (const float*)d_in[0];
    }
    float* out = (float*)d_out;

    cudaFuncSetAttribute(rsnn_kernel, cudaFuncAttributeMaxDynamicSharedMemorySize, SMEM_TOTAL);

    dim3 cg(NN / 32, NN / 32), cb(32, 32);
    prep_kernel<<<cg, cb>>>(rec);
    rsnn_kernel<<<CTAS, THREADS, SMEM_TOTAL>>>(x, out);
}